// round 3
// baseline (speedup 1.0000x reference)
#include <cuda_runtime.h>
#include <float.h>
#include <math.h>

// Problem geometry
#define HH 512
#define WW 512
#define SLICES 128                 // B*P = 64*2
#define NB 32                      // blocks per slice
#define TPB 256                    // threads per block
#define NBLOCKS (SLICES*NB)        // 4096
#define ELEMS_PER_SLICE (HH*WW)    // 262144
#define ELEMS_PER_BLOCK (ELEMS_PER_SLICE/NB)   // 8192
#define VEC4_PER_BLOCK  (ELEMS_PER_BLOCK/4)    // 2048
#define VEC4_PER_THREAD (VEC4_PER_BLOCK/TPB)   // 8

// Per-block partials (static device scratch; no allocation)
__device__ float g_s [NBLOCKS];
__device__ float g_sx[NBLOCKS];
__device__ float g_sy[NBLOCKS];
__device__ float g_tv[NBLOCKS];
__device__ int   g_ti[NBLOCKS];
__device__ unsigned int g_count;   // zero-initialized; reset by last block each run

__global__ __launch_bounds__(TPB)
void dsnt_fused(const float4* __restrict__ inp, const float4* __restrict__ tgt,
                float* __restrict__ out)
{
    const int blk   = blockIdx.x;          // 0..NBLOCKS-1
    const int slice = blk >> 5;            // /NB
    const int sub   = blk & (NB-1);
    const int tid   = threadIdx.x;
    const int wid   = tid >> 5;
    const int lid   = tid & 31;

    const int slice_base4 = slice * (ELEMS_PER_SLICE/4);
    const int chunk_base4 = sub * VEC4_PER_BLOCK;

    float s = 0.f, sx = 0.f, sy = 0.f;
    float tv = -FLT_MAX;
    int   ti = 0x7fffffff;

#pragma unroll
    for (int k = 0; k < VEC4_PER_THREAD; k++) {
        const int local4 = k * TPB + tid;               // block-stride, coalesced
        const int g4     = slice_base4 + chunk_base4 + local4;
        const float4 v = __ldcs(&inp[g4]);              // streaming: read-once
        const float4 t = __ldcs(&tgt[g4]);

        const int ei  = (chunk_base4 + local4) << 2;    // element index in slice
        const int row = ei >> 9;                        // /512
        const int col = ei & 511;

        const float e0 = __expf(v.x);
        const float e1 = __expf(v.y);
        const float e2 = __expf(v.z);
        const float e3 = __expf(v.w);
        const float es = (e0 + e1) + (e2 + e3);
        s  += es;
        sx += e0*(float)(col+1) + e1*(float)(col+2)
            + e2*(float)(col+3) + e3*(float)(col+4);
        sy += es * (float)(row+1);

        // target running argmax (indices visited in increasing order per thread)
        if (t.x > tv) { tv = t.x; ti = ei;     }
        if (t.y > tv) { tv = t.y; ti = ei + 1; }
        if (t.z > tv) { tv = t.z; ti = ei + 2; }
        if (t.w > tv) { tv = t.w; ti = ei + 3; }
    }

    // ---- warp reduce ----
#pragma unroll
    for (int off = 16; off > 0; off >>= 1) {
        s  += __shfl_down_sync(0xffffffffu, s,  off);
        sx += __shfl_down_sync(0xffffffffu, sx, off);
        sy += __shfl_down_sync(0xffffffffu, sy, off);
        float ov = __shfl_down_sync(0xffffffffu, tv, off);
        int   oi = __shfl_down_sync(0xffffffffu, ti, off);
        if (ov > tv || (ov == tv && oi < ti)) { tv = ov; ti = oi; }
    }

    __shared__ float sh_s[8], sh_sx[8], sh_sy[8], sh_tv[8];
    __shared__ int   sh_ti[8];
    if (lid == 0) { sh_s[wid]=s; sh_sx[wid]=sx; sh_sy[wid]=sy; sh_tv[wid]=tv; sh_ti[wid]=ti; }
    __syncthreads();

    if (wid == 0) {
        s  = (lid < 8) ? sh_s [lid] : 0.f;
        sx = (lid < 8) ? sh_sx[lid] : 0.f;
        sy = (lid < 8) ? sh_sy[lid] : 0.f;
        tv = (lid < 8) ? sh_tv[lid] : -FLT_MAX;
        ti = (lid < 8) ? sh_ti[lid] : 0x7fffffff;
#pragma unroll
        for (int off = 4; off > 0; off >>= 1) {
            s  += __shfl_down_sync(0xffffffffu, s,  off);
            sx += __shfl_down_sync(0xffffffffu, sx, off);
            sy += __shfl_down_sync(0xffffffffu, sy, off);
            float ov = __shfl_down_sync(0xffffffffu, tv, off);
            int   oi = __shfl_down_sync(0xffffffffu, ti, off);
            if (ov > tv || (ov == tv && oi < ti)) { tv = ov; ti = oi; }
        }
        if (lid == 0) {
            g_s [blk] = s;
            g_sx[blk] = sx;
            g_sy[blk] = sy;
            g_tv[blk] = tv;
            g_ti[blk] = ti;
        }
    }

    // ---- last-block final reduction ----
    __shared__ bool amLast;
    __threadfence();                        // make partials visible
    if (tid == 0)
        amLast = (atomicAdd(&g_count, 1u) == NBLOCKS - 1u);
    __syncthreads();
    if (!amLast) return;

    // This block is last: all partials are globally visible.
    __shared__ float sh_px[SLICES], sh_py[SLICES], sh_tx[SLICES], sh_ty[SLICES];
    __shared__ double sh_red[64];

    // One warp per slice, 16 slices per warp (8 warps). Lane l reads partial l
    // of slice sl -> fully coalesced (consecutive 32 floats per array).
#pragma unroll 1
    for (int sl = wid; sl < SLICES; sl += 8) {
        const int id = sl * NB + lid;
        double S  = (double)g_s [id];
        double SX = (double)g_sx[id];
        double SY = (double)g_sy[id];
        float  mv = g_tv[id];
        int    mi = g_ti[id];
#pragma unroll
        for (int off = 16; off > 0; off >>= 1) {
            S  += __shfl_down_sync(0xffffffffu, S,  off);
            SX += __shfl_down_sync(0xffffffffu, SX, off);
            SY += __shfl_down_sync(0xffffffffu, SY, off);
            float ov = __shfl_down_sync(0xffffffffu, mv, off);
            int   oi = __shfl_down_sync(0xffffffffu, mi, off);
            if (ov > mv || (ov == mv && oi < mi)) { mv = ov; mi = oi; }
        }
        if (lid == 0) {
            sh_px[sl] = (float)(SX / (S * 512.0));
            sh_py[sl] = (float)(SY / (S * 512.0));
            sh_tx[sl] = (float)((mi & 511) + 1) * (1.0f / 512.0f);
            sh_ty[sl] = (float)((mi >> 9)  + 1) * (1.0f / 512.0f);
        }
    }
    __syncthreads();

    if (tid < 64) {
        const int p0 = 2 * tid, p1 = 2 * tid + 1;
        const double px0 = sh_px[p0], py0 = sh_py[p0];
        const double px1 = sh_px[p1], py1 = sh_py[p1];
        const double tx0 = sh_tx[p0], ty0 = sh_ty[p0];
        const double tx1 = sh_tx[p1], ty1 = sh_ty[p1];

        const double dx0 = tx0 - px0, dy0 = ty0 - py0;
        const double dx1 = tx1 - px1, dy1 = ty1 - py1;
        const double ed  = sqrt(dx0*dx0 + dy0*dy0) + sqrt(dx1*dx1 + dy1*dy1);

        const double pvx = px0 - px1, pvy = py0 - py1;
        const double tvx = tx0 - tx1, tvy = ty0 - ty1;
        const double pd  = sqrt(pvx*pvx + pvy*pvy);
        const double td  = sqrt(tvx*tvx + tvy*tvy);
        const double dot = pvx*tvx + pvy*tvy;

        sh_red[tid] = ed + fabs(pd - td) + (1.0 - cos(dot / (pd * td)));
    }
    __syncthreads();

    if (tid == 0) {
        double acc = 0.0;
#pragma unroll
        for (int i = 0; i < 64; i++) acc += sh_red[i];
        out[0] = (float)(acc / 64.0);
        g_count = 0;                        // reset for next graph replay
    }
}

extern "C" void kernel_launch(void* const* d_in, const int* in_sizes, int n_in,
                              void* d_out, int out_size)
{
    const float4* inp = (const float4*)d_in[0];
    const float4* tgt = (const float4*)d_in[1];
    float* out = (float*)d_out;

    dsnt_fused<<<NBLOCKS, TPB>>>(inp, tgt, out);
}